// round 3
// baseline (speedup 1.0000x reference)
#include <cuda_runtime.h>
#include <cuda_bf16.h>
#include <cstdint>

// AFM forward, algebraically collapsed (softmax over size-1 axis == 1):
//   x[b]  = 0.5*(||sum_f emb_f||^2 - sum_f ||emb_f||^2)
//   out[b] = sigmoid(x[b]*out_kernel + out_bias)
//
// Layout: QUARTER-WARP per (row, field-group). 4 warps per row:
//   warp-quarter q owns fields 7q .. 7q+6 (quarter 3 has 5 fields).
//   lane = f_local*4 + slice ; exactly ONE id load + ONE 16B gather per lane,
//   with the id loaded directly (no shuffle on the address path).
// 16384 warps -> 64 warps/SM (full occupancy), 2 waves. Reduction:
//   3 shuffle levels over the field dim, then a tiny smem combine per block.

#define B_ROWS   4096
#define N_SPARSE 26
#define VOCAB    100000

__global__ void __launch_bounds__(256) afm_gather_kernel(
    const int*    __restrict__ ids,     // [B, 26]
    const float4* __restrict__ table,   // [26, VOCAB, 4] float4 units
    const float*  __restrict__ out_k,   // [1]
    const float*  __restrict__ out_b,   // [1]
    float*        __restrict__ out)     // [B]
{
    const unsigned FULL = 0xffffffffu;

    __shared__ float4 sS[2][4][4];   // [row_in_block][quarter][slice] partial sum-vec
    __shared__ float  sQ[2][4][4];   // partial sum of squares

    const int tid     = threadIdx.x;
    const int warp    = tid >> 5;         // 0..7
    const int lane    = tid & 31;
    const int rib     = warp >> 2;        // row in block: 0/1
    const int quarter = warp & 3;         // field group 0..3
    const int row     = blockIdx.x * 2 + rib;

    const int f_local = lane >> 2;        // 0..7 (slot 7 idle; quarter3 slots 5,6 idle)
    const int slice   = lane & 3;         // which float4 of the embedding
    const int field   = quarter * 7 + f_local;
    const bool act    = (f_local < 7) && (field < N_SPARSE);

    // One direct id load + one 16B gather per lane. Address chain: LDG -> LDG.
    float4 v = make_float4(0.f, 0.f, 0.f, 0.f);
    if (act) {
        const int id = __ldg(ids + row * N_SPARSE + field);
        v = __ldg(table + (size_t)field * (VOCAB * 4) + (size_t)id * 4 + slice);
    }
    float q = v.x * v.x + v.y * v.y + v.z * v.z + v.w * v.w;

    // Reduce over the field dimension (lane bits 2,3,4): 3 levels.
    float4 S = v;
    #pragma unroll
    for (int d = 4; d <= 16; d <<= 1) {
        S.x += __shfl_xor_sync(FULL, S.x, d);
        S.y += __shfl_xor_sync(FULL, S.y, d);
        S.z += __shfl_xor_sync(FULL, S.z, d);
        S.w += __shfl_xor_sync(FULL, S.w, d);
        q   += __shfl_xor_sync(FULL, q, d);
    }

    if (lane < 4) {                       // lanes 0..3 hold per-slice partials
        sS[rib][quarter][lane] = S;
        sQ[rib][quarter][lane] = q;
    }
    __syncthreads();

    // Final combine: lanes 0..3 of warp 0 (row 0) and warp 4 (row 1).
    // Must sum S over quarters BEFORE squaring.
    if (quarter == 0 && lane < 4) {
        float4 St = sS[rib][0][lane];
        float  qt = sQ[rib][0][lane];
        #pragma unroll
        for (int qq = 1; qq < 4; ++qq) {
            const float4 p = sS[rib][qq][lane];
            St.x += p.x; St.y += p.y; St.z += p.z; St.w += p.w;
            qt   += sQ[rib][qq][lane];
        }
        float s2 = St.x * St.x + St.y * St.y + St.z * St.z + St.w * St.w;
        // sum s2, qt over the 4 slice lanes
        s2 += __shfl_xor_sync(0xFu, s2, 1); s2 += __shfl_xor_sync(0xFu, s2, 2);
        qt += __shfl_xor_sync(0xFu, qt, 1); qt += __shfl_xor_sync(0xFu, qt, 2);
        if (lane == 0) {
            const float t = s2 - qt;                 // == 2 * sum_{i<j} e_i.e_j
            const float z = 0.5f * t * __ldg(out_k) + __ldg(out_b);
            out[row] = 1.0f / (1.0f + __expf(-z));
        }
    }
}

extern "C" void kernel_launch(void* const* d_in, const int* in_sizes, int n_in,
                              void* d_out, int out_size)
{
    (void)in_sizes; (void)n_in; (void)out_size;
    const int*    ids   = (const int*)   d_in[1];
    const float4* table = (const float4*)d_in[2];
    const float*  out_k = (const float*) d_in[7];
    const float*  out_b = (const float*) d_in[8];
    float*        out   = (float*)       d_out;

    const int threads = 256;               // 8 warps = 2 rows per block
    const int blocks  = B_ROWS / 2;        // 2048 blocks
    afm_gather_kernel<<<blocks, threads>>>(ids, table, out_k, out_b, out);
}

// round 4
// speedup vs baseline: 1.3527x; 1.3527x over previous
#include <cuda_runtime.h>
#include <cuda_bf16.h>
#include <cstdint>

// AFM forward, algebraically collapsed (softmax over size-1 axis == 1):
//   x[b]   = 0.5*(||sum_f emb_f||^2 - sum_f ||emb_f||^2)
//   out[b] = sigmoid(x[b]*out_kernel + out_bias)
//
// Shape: ONE WARP PER ROW (best measured: R2 = 6.88us). Changes vs R2:
//  * ids loaded DIRECTLY per lane (4-lane broadcast, 32B/warp) -- no __shfl
//    on the address path, so all 4 id LDGs + 4 gather LDGs front-batch and
//    the id->gather chain is two back-to-back memory ops.
//  * 512-thread blocks (256 blocks) to reduce CTA-scheduling overhead.

#define B_ROWS   4096
#define N_SPARSE 26
#define VOCAB    100000

__global__ void __launch_bounds__(512) afm_gather_kernel(
    const int*    __restrict__ ids,     // [B, 26]
    const float4* __restrict__ table,   // [26, VOCAB, 4] float4 units
    const float*  __restrict__ out_k,   // [1]
    const float*  __restrict__ out_b,   // [1]
    float*        __restrict__ out)     // [B]
{
    const unsigned FULL = 0xffffffffu;
    const int gtid = blockIdx.x * blockDim.x + threadIdx.x;
    const int row  = gtid >> 5;           // one warp per row
    const int lane = threadIdx.x & 31;
    if (row >= B_ROWS) return;

    const int slice = lane & 3;            // which float4 of the 16-float emb
    const int fg    = lane >> 2;           // field-in-group 0..7

    const int* rid = ids + row * N_SPARSE;

    // Round r handles field f = r*8 + fg. All id loads are independent and
    // issue first; each gather depends only on its own id.
    float4 S = make_float4(0.f, 0.f, 0.f, 0.f);
    float  q = 0.f;

    #pragma unroll
    for (int r = 0; r < 4; ++r) {
        const int  f   = r * 8 + fg;
        const bool act = (f < N_SPARSE);    // round 3: only fg 0,1 active
        if (act) {
            const int id = __ldg(rid + f);  // 4-lane broadcast, 32B/warp
            const float4 v = __ldg(table + (size_t)f * (VOCAB * 4)
                                         + (size_t)id * 4 + slice);
            S.x += v.x; S.y += v.y; S.z += v.z; S.w += v.w;
            q   += v.x * v.x + v.y * v.y + v.z * v.z + v.w * v.w;
        }
    }

    // Reduce S and q over the field dimension (lane bits 2,3,4): 3 levels.
    #pragma unroll
    for (int d = 4; d <= 16; d <<= 1) {
        S.x += __shfl_xor_sync(FULL, S.x, d);
        S.y += __shfl_xor_sync(FULL, S.y, d);
        S.z += __shfl_xor_sync(FULL, S.z, d);
        S.w += __shfl_xor_sync(FULL, S.w, d);
        q   += __shfl_xor_sync(FULL, q, d);
    }

    // Lanes 0..3 now hold per-slice totals. |S|^2 per slice, then sum the
    // 4 slices (lane bits 0,1) together with q.
    float s2 = S.x * S.x + S.y * S.y + S.z * S.z + S.w * S.w;
    s2 += __shfl_xor_sync(FULL, s2, 1);
    s2 += __shfl_xor_sync(FULL, s2, 2);
    q  += __shfl_xor_sync(FULL, q, 1);   // harmless on upper lanes
    q  += __shfl_xor_sync(FULL, q, 2);

    if (lane == 0) {
        const float t = s2 - q;                  // == 2 * sum_{i<j} e_i.e_j
        const float z = 0.5f * t * __ldg(out_k) + __ldg(out_b);
        out[row] = 1.0f / (1.0f + __expf(-z));
    }
}

extern "C" void kernel_launch(void* const* d_in, const int* in_sizes, int n_in,
                              void* d_out, int out_size)
{
    (void)in_sizes; (void)n_in; (void)out_size;
    const int*    ids   = (const int*)   d_in[1];
    const float4* table = (const float4*)d_in[2];
    const float*  out_k = (const float*) d_in[7];
    const float*  out_b = (const float*) d_in[8];
    float*        out   = (float*)       d_out;

    const int threads = 512;                    // 16 warps = 16 rows / block
    const int blocks  = (B_ROWS * 32 + threads - 1) / threads;   // 256 blocks
    afm_gather_kernel<<<blocks, threads>>>(ids, table, out_k, out_b, out);
}